// round 15
// baseline (speedup 1.0000x reference)
#include <cuda_runtime.h>
#include <math.h>

typedef unsigned long long u64;

// Problem shape (fixed): B=2, S=8, N=2048, D=3
#define NPTS   2048
#define NSETS  16                    // B*S

// Main tile kernel geometry: block = (set, rowchunk, colchunk)
#define TPB    256
#define RPT    2                     // rows per thread
#define ROWS_B (TPB * RPT)           // 512 rows per block
#define COLS_B 256                   // 256 cols per block
#define NRC    (NPTS / ROWS_B)       // 4 rowchunks
#define NCC    (NPTS / COLS_B)       // 8 colchunks
#define NBLK1  (NSETS * NRC * NCC)   // 512 blocks

#define CPAIRS (COLS_B / 2)          // 128 packed col-pairs

// Finalize kernel
#define NBLK2  (NSETS * 2)           // 32 blocks (set, dir)
#define QPT2   (NPTS / TPB)          // 8 queries per thread

#define FLTMAX_BITS 0x7F7FFFFFu

// g_min[0][set][i]: min d^2 for X query i (over targets)   [dir 0]
// g_min[1][set][j]: min d^2 for target j (over X)           [dir 1]
__device__ unsigned g_min[2][NSETS][NPTS];

__device__ float g_loss_part[NBLK2];
__device__ float g_cent_part[NBLK2][3];
__device__ unsigned int g_ctr = 0;   // self-resetting completion counter

__device__ __forceinline__ float smooth_l1(float a, float b) {
    float d = fabsf(a - b);
    return (d < 1.0f) ? (0.5f * d * d) : (d - 0.5f);
}

// Blackwell packed f32x2 ops (PTX-only)
#define PACK2(d, lo, hi) \
    asm("mov.b64 %0, {%1, %2};" : "=l"(d) : "f"(lo), "f"(hi))
#define UNPACK2(lo, hi, s) \
    asm("mov.b64 {%0, %1}, %2;" : "=f"(lo), "=f"(hi) : "l"(s))
#define ADD2(d, a, b) \
    asm("add.rn.f32x2 %0, %1, %2;" : "=l"(d) : "l"(a), "l"(b))
#define FMA2_INIT(d, a, b, c) \
    asm("fma.rn.f32x2 %0, %1, %2, %3;" : "=l"(d) : "l"(a), "l"(b), "l"(c))
#define FMA2_ACC(d, a, b) \
    asm("fma.rn.f32x2 %0, %1, %2, %0;" : "+l"(d) : "l"(a), "l"(b))

// ---------------------------------------------------------------------------
// Kernel 0: init the min arrays to +FLT_MAX bits.
// ---------------------------------------------------------------------------
__global__ void init_kernel() {
    unsigned* p = &g_min[0][0][0];
    int n = 2 * NSETS * NPTS;
    for (int i = blockIdx.x * blockDim.x + threadIdx.x; i < n;
         i += gridDim.x * blockDim.x)
        p[i] = FLTMAX_BITS;
}

// ---------------------------------------------------------------------------
// Kernel 1: dual-direction distance tile. Each d(i,j) computed ONCE, feeds
// both the row (X->target) and column (target->X) running minima.
// ---------------------------------------------------------------------------
__global__ __launch_bounds__(TPB)
void tile_kernel(const float* __restrict__ Xv, const float* __restrict__ Tv)
{
    const int tid  = threadIdx.x;
    const int blk  = blockIdx.x;
    const int set  = blk >> 5;             // 32 blocks per set
    const int rc   = (blk >> 3) & 3;       // rowchunk
    const int cc   = blk & 7;              // colchunk
    const int wid  = tid >> 5;
    const int lane = tid & 31;

    const float* __restrict__ rowg = Xv + set * NPTS * 3;   // rows  = X points
    const float* __restrict__ colg = Tv + set * NPTS * 3;   // cols  = targets

    // Packed column tile: cA[jp] = {(-2x_j0,-2x_j1), (-2y_j0,-2y_j1)}
    //                     cB[jp] = {(-2z_j0,-2z_j1), ( t2_j0, t2_j1)}
    __shared__ ulonglong2 cA[CPAIRS];      // 2 KB
    __shared__ ulonglong2 cB[CPAIRS];      // 2 KB
    __shared__ float scol[8][COLS_B];      // 8 KB: per-warp column mins

    for (int i = tid; i < COLS_B; i += TPB) {
        int j = cc * COLS_B + i;
        float x = colg[j * 3 + 0];
        float y = colg[j * 3 + 1];
        float z = colg[j * 3 + 2];
        float n = x * x;
        n = fmaf(y, y, n);
        n = fmaf(z, z, n);
        int jp = i >> 1, l = i & 1;
        float* fA = (float*)&cA[jp];
        float* fB = (float*)&cB[jp];
        fA[0 + l] = -2.0f * x;
        fA[2 + l] = -2.0f * y;
        fB[0 + l] = -2.0f * z;
        fB[2 + l] = n;
    }

    // This thread's RPT rows.
    int   ri[RPT];
    u64   qx2[RPT], qy2[RPT], qz2[RPT], p2d[RPT];
#pragma unroll
    for (int r = 0; r < RPT; r++) {
        ri[r] = rc * ROWS_B + r * TPB + tid;
        float x = rowg[ri[r] * 3 + 0];
        float y = rowg[ri[r] * 3 + 1];
        float z = rowg[ri[r] * 3 + 2];
        float n = x * x;
        n = fmaf(y, y, n);
        n = fmaf(z, z, n);
        PACK2(qx2[r], x, x);
        PACK2(qy2[r], y, y);
        PACK2(qz2[r], z, z);
        PACK2(p2d[r], n, n);
    }
    float rmin[RPT];
#pragma unroll
    for (int r = 0; r < RPT; r++) rmin[r] = 3.0e38f;

    __syncthreads();

    // Main loop: per col-pair, 4 true d^2 values (2 rows x 2 cols).
#pragma unroll 4
    for (int jp = 0; jp < CPAIRS; jp++) {
        ulonglong2 va = cA[jp];   // broadcast: all lanes same address
        ulonglong2 vb = cB[jp];

        float d0[RPT], d1[RPT];
#pragma unroll
        for (int r = 0; r < RPT; r++) {
            u64 acc;
            ADD2(acc, vb.y, p2d[r]);             // (t2 + p2) pair
            FMA2_ACC(acc, qx2[r], va.x);
            FMA2_ACC(acc, qy2[r], va.y);
            FMA2_ACC(acc, qz2[r], vb.x);
            float a, b;
            UNPACK2(a, b, acc);
            d0[r] = fmaxf(a, 0.0f);              // clamp: uint-monotone + exact
            d1[r] = fmaxf(b, 0.0f);
            rmin[r] = fminf(rmin[r], fminf(d0[r], d1[r]));
        }
        // Column mins: reduce this thread's rows, then across the warp's 32
        // threads (= 32 distinct row groups) with exact REDUX.
        float cm0 = fminf(d0[0], d0[1]);
        float cm1 = fminf(d1[0], d1[1]);
        unsigned u0 = __reduce_min_sync(0xffffffffu, __float_as_uint(cm0));
        unsigned u1 = __reduce_min_sync(0xffffffffu, __float_as_uint(cm1));
        if (lane == 0) {
            scol[wid][2 * jp]     = __uint_as_float(u0);
            scol[wid][2 * jp + 1] = __uint_as_float(u1);
        }
    }

    // Row mins -> global (exact atomic min on positive-float bits).
#pragma unroll
    for (int r = 0; r < RPT; r++)
        atomicMin(&g_min[0][set][ri[r]], __float_as_uint(rmin[r]));

    __syncthreads();

    // Column mins: merge the 8 warp slices, then global atomic min.
    for (int c = tid; c < COLS_B; c += TPB) {
        float m = scol[0][c];
#pragma unroll
        for (int w = 1; w < 8; w++) m = fminf(m, scol[w][c]);
        atomicMin(&g_min[1][set][cc * COLS_B + c], __float_as_uint(m));
    }
}

// ---------------------------------------------------------------------------
// Kernel 2: losses from the min arrays + centroid sums + final reduction.
// ---------------------------------------------------------------------------
__global__ __launch_bounds__(TPB)
void finalize_kernel(const float* __restrict__ Xv, const float* __restrict__ Tv,
                     const float* __restrict__ w, float* __restrict__ out)
{
    const int tid = threadIdx.x;
    const int blk = blockIdx.x;            // 0..31
    const int set = blk >> 1;
    const int dir = blk & 1;               // 0: queries=X, 1: queries=target

    const float* __restrict__ qg = (dir == 0 ? Xv : Tv) + set * NPTS * 3;
    const float* __restrict__ dg = (dir == 0 ? Tv : Xv) + set * NPTS * 3;
    const unsigned* __restrict__ mins = g_min[dir][set];

    __shared__ float4 red4[TPB];
    __shared__ unsigned int is_last;

    float sl = 0.0f, cx = 0.0f, cy = 0.0f, cz = 0.0f;
#pragma unroll
    for (int k = 0; k < QPT2; k++) {
        int qi = k * TPB + tid;
        float qx = qg[qi * 3 + 0];
        float qy = qg[qi * 3 + 1];
        float qz = qg[qi * 3 + 2];
        float d2 = __uint_as_float(mins[qi]);
        if (d2 < 0.98f) {
            // Exact: d2<1 forces every per-coord |diff|<1, so the summed
            // smooth_l1 over coords equals 0.5*d2 exactly.
            sl += 0.5f * d2;
        } else {
            // Cold exact fallback: brute global argmin + true smooth_l1.
            float p2 = qx * qx;
            p2 = fmaf(qy, qy, p2);
            p2 = fmaf(qz, qz, p2);
            float best = 3.4e38f;
            int bj = 0;
            for (int j = 0; j < NPTS; j++) {
                float tx = dg[j * 3 + 0];
                float ty = dg[j * 3 + 1];
                float tz = dg[j * 3 + 2];
                float kk = tx * tx;
                kk = fmaf(ty, ty, kk);
                kk = fmaf(tz, tz, kk);
                kk = fmaf(-2.0f * qx, tx, kk);
                kk = fmaf(-2.0f * qy, ty, kk);
                kk = fmaf(-2.0f * qz, tz, kk);
                if (kk < best) { best = kk; bj = j; }
            }
            sl += smooth_l1(qx, dg[bj * 3 + 0]);
            sl += smooth_l1(qy, dg[bj * 3 + 1]);
            sl += smooth_l1(qz, dg[bj * 3 + 2]);
        }
        cx += qx; cy += qy; cz += qz;
    }

    // Deterministic block reduction (fixed tree order).
    red4[tid] = make_float4(sl, cx, cy, cz);
    __syncthreads();
    for (int s = TPB / 2; s > 0; s >>= 1) {
        if (tid < s) {
            float4 a = red4[tid];
            float4 b = red4[tid + s];
            red4[tid] = make_float4(a.x + b.x, a.y + b.y, a.z + b.z, a.w + b.w);
        }
        __syncthreads();
    }
    if (tid == 0) {
        float4 r = red4[0];
        g_loss_part[blk]    = r.x;
        g_cent_part[blk][0] = r.y;
        g_cent_part[blk][1] = r.z;
        g_cent_part[blk][2] = r.w;
        __threadfence();
        unsigned int v = atomicAdd(&g_ctr, 1u);
        is_last = (v == NBLK2 - 1) ? 1u : 0u;
    }
    __syncthreads();

    // Last block finalizes (deterministic; counter self-resets for replay).
    if (is_last && tid < 32) {
        __threadfence();
        const int t = tid;
        float lp = 0.0f, lc = 0.0f;
        if (t < NSETS) {
            float s = g_loss_part[t * 2 + 0] + g_loss_part[t * 2 + 1];
            lp = s * (1.0f / (float)(NPTS * 3)) * w[t];

            const float inv_n = 1.0f / (float)NPTS;
            lc += smooth_l1(g_cent_part[t * 2 + 0][0] * inv_n,
                            g_cent_part[t * 2 + 1][0] * inv_n);
            lc += smooth_l1(g_cent_part[t * 2 + 0][1] * inv_n,
                            g_cent_part[t * 2 + 1][1] * inv_n);
            lc += smooth_l1(g_cent_part[t * 2 + 0][2] * inv_n,
                            g_cent_part[t * 2 + 1][2] * inv_n);
        }
#pragma unroll
        for (int o = 16; o > 0; o >>= 1) {
            lp += __shfl_down_sync(0xffffffff, lp, o);
            lc += __shfl_down_sync(0xffffffff, lc, o);
        }
        if (t == 0) {
            out[0] = lp * 0.5f;          // / B
            out[1] = lc * (1.0f / 6.0f); // / (B*3)
            g_ctr = 0;                   // reset for next graph replay
        }
    }
}

extern "C" void kernel_launch(void* const* d_in, const int* in_sizes, int n_in,
                              void* d_out, int out_size) {
    const float* Xv = (const float*)d_in[0];
    const float* Tv = (const float*)d_in[1];
    const float* w  = (const float*)d_in[2];
    float* out = (float*)d_out;

    init_kernel<<<64, 256>>>();
    tile_kernel<<<NBLK1, TPB>>>(Xv, Tv);
    finalize_kernel<<<NBLK2, TPB>>>(Xv, Tv, w, out);
}

// round 16
// speedup vs baseline: 5.3723x; 5.3723x over previous
#include <cuda_runtime.h>
#include <math.h>

typedef unsigned long long u64;

// Problem shape (fixed): B=2, S=8, N=2048, D=3
#define NPTS   2048
#define TPB    256
#define QPT    2                    // queries per thread
#define SPLIT  4                    // DB split across lanes of a group
#define QPB    128                  // queries per block = (TPB/SPLIT)*QPT
#define CHUNKS (NPTS / QPB)         // 16
#define NSETS  16                   // B*S
#define NBLK   (NSETS * 2 * CHUNKS) // 512 blocks -> single wave

#define NJP    (NPTS / 2)           // 1024 lane-pairs total
#define QJP    (NJP / SPLIT)        // 256 lane-pairs per quarter
#define QPAD   (QJP + 1)            // quarters offset by 4 banks

__device__ float g_loss_part[NBLK];
__device__ float g_cent_part[NBLK][3];
__device__ unsigned int g_ctr = 0;   // self-resetting completion counter

__device__ __forceinline__ float smooth_l1(float a, float b) {
    float d = fabsf(a - b);
    return (d < 1.0f) ? (0.5f * d * d) : (d - 0.5f);
}

// Blackwell packed f32x2 FMA (only reachable via PTX)
#define FMA2(d, a, b, c) \
    asm("fma.rn.f32x2 %0, %1, %2, %3;" : "=l"(d) : "l"(a), "l"(b), "l"(c))
#define PACK2(d, lo, hi) \
    asm("mov.b64 %0, {%1, %2};" : "=l"(d) : "f"(lo), "f"(hi))
#define UNPACK2(lo, hi, s) \
    asm("mov.b64 {%0, %1}, %2;" : "=f"(lo), "=f"(hi) : "l"(s))

__global__ __launch_bounds__(TPB, 4)
void chamfer_kernel(const float* __restrict__ Xv, const float* __restrict__ Tv,
                    const float* __restrict__ w, float* __restrict__ out)
{
    const int tid   = threadIdx.x;
    const int blk   = blockIdx.x;
    const int set   = blk / (2 * CHUNKS);
    const int rem   = blk % (2 * CHUNKS);
    const int dir   = rem / CHUNKS;      // 0: queries=X_v, db=target ; 1: swapped
    const int chunk = rem % CHUNKS;

    const float* __restrict__ qg = (dir == 0 ? Xv : Tv) + set * NPTS * 3;
    const float* __restrict__ dg = (dir == 0 ? Tv : Xv) + set * NPTS * 3;

    // DB tile in quarters, interleaved for f32x2 over consecutive-j pairs.
    // shA[qt][loc] = { (-2x_j, -2x_{j+1}) , (-2y_j, -2y_{j+1}) },  jp = qt*QJP + loc
    // shB[qt][loc] = { (-2z_j, -2z_{j+1}) , ( t2_j,  t2_{j+1}) }
    __shared__ ulonglong2 shA[SPLIT][QPAD];   // ~16.1 KB
    __shared__ ulonglong2 shB[SPLIT][QPAD];   // ~16.1 KB
    __shared__ float4 red4[TPB];              // 4 KB
    __shared__ unsigned int is_last;

    for (int i = tid; i < NPTS; i += TPB) {
        float x = dg[i * 3 + 0];
        float y = dg[i * 3 + 1];
        float z = dg[i * 3 + 2];
        float n = x * x;
        n = fmaf(y, y, n);
        n = fmaf(z, z, n);
        int jp = i >> 1, l = i & 1;
        int qt = jp >> 8, loc = jp & (QJP - 1);
        float* fA = (float*)&shA[qt][loc];
        float* fB = (float*)&shB[qt][loc];
        fA[0 + l] = -2.0f * x;
        fA[2 + l] = -2.0f * y;
        fB[0 + l] = -2.0f * z;
        fB[2 + l] = n;
    }
    __syncthreads();

    // Group g owns 2 queries; lane's quarter = tid&3.
    const int g    = tid >> 2;           // 0..63
    const int qt   = tid & 3;
    const int qi0  = chunk * QPB + g;            // query 0
    const int qi1  = chunk * QPB + 64 + g;       // query 1
    const float qx0 = qg[qi0 * 3 + 0], qy0 = qg[qi0 * 3 + 1], qz0 = qg[qi0 * 3 + 2];
    const float qx1 = qg[qi1 * 3 + 0], qy1 = qg[qi1 * 3 + 1], qz1 = qg[qi1 * 3 + 2];
    float p20 = qx0 * qx0; p20 = fmaf(qy0, qy0, p20); p20 = fmaf(qz0, qz0, p20);
    float p21 = qx1 * qx1; p21 = fmaf(qy1, qy1, p21); p21 = fmaf(qz1, qz1, p21);
    u64 qx20, qy20, qz20, qx21, qy21, qz21;
    PACK2(qx20, qx0, qx0); PACK2(qy20, qy0, qy0); PACK2(qz20, qz0, qz0);
    PACK2(qx21, qx1, qx1); PACK2(qy21, qy1, qy1); PACK2(qz21, qz1, qz1);

    // 4 independent FMNMX chains (2 per query: even/odd candidate lane).
    float m00 = 3.0e38f, m01 = 3.0e38f, m10 = 3.0e38f, m11 = 3.0e38f;
    const ulonglong2* __restrict__ pA = shA[qt];
    const ulonglong2* __restrict__ pB = shB[qt];

    // key: t2_j - 2*q.t_j  (p2 constant per query -> added back after loop).
#pragma unroll 4
    for (int loc = 0; loc < QJP; loc++) {
        ulonglong2 va = pA[loc];   // {mx2, my2}
        ulonglong2 vb = pB[loc];   // {mz2, t2x2}

        u64 a0 = vb.y;
        FMA2(a0, qx20, va.x, a0);
        FMA2(a0, qy20, va.y, a0);
        FMA2(a0, qz20, vb.x, a0);
        u64 a1 = vb.y;
        FMA2(a1, qx21, va.x, a1);
        FMA2(a1, qy21, va.y, a1);
        FMA2(a1, qz21, vb.x, a1);

        float d00, d01, d10, d11;
        UNPACK2(d00, d01, a0);
        UNPACK2(d10, d11, a1);
        m00 = fminf(m00, d00);
        m01 = fminf(m01, d01);
        m10 = fminf(m10, d10);
        m11 = fminf(m11, d11);
    }

    // Merge even/odd, then across the 4-lane group (2 shfl_xor).
    float mk0 = fminf(m00, m01);
    float mk1 = fminf(m10, m11);
    mk0 = fminf(mk0, __shfl_xor_sync(0xffffffffu, mk0, 1));
    mk0 = fminf(mk0, __shfl_xor_sync(0xffffffffu, mk0, 2));
    mk1 = fminf(mk1, __shfl_xor_sync(0xffffffffu, mk1, 1));
    mk1 = fminf(mk1, __shfl_xor_sync(0xffffffffu, mk1, 2));

    // Lane qt==0 computes partials via the exact 0.5*d2 identity.
    float sl = 0.0f, cx = 0.0f, cy = 0.0f, cz = 0.0f;
    if (qt == 0) {
        float qxs[2] = {qx0, qx1}, qys[2] = {qy0, qy1}, qzs[2] = {qz0, qz1};
        float d2s[2] = {p20 + mk0, p21 + mk1};
#pragma unroll
        for (int q = 0; q < 2; q++) {
            float d2 = d2s[q];
            if (d2 < 0.98f) {
                // Exact: d2<1 forces every per-coord |diff|<1, so the summed
                // smooth_l1 over coords equals 0.5*d2 exactly.
                sl += 0.5f * fmaxf(d2, 0.0f);
            } else {
                // Cold exact fallback: smem argmin rescan + true smooth_l1.
                float best = 3.4e38f;
                int bj = 0;
                for (int j = 0; j < NPTS; j++) {
                    int jp = j >> 1, l = j & 1;
                    int qq = jp >> 8, loc = jp & (QJP - 1);
                    const float* fA = (const float*)&shA[qq][loc];
                    const float* fB = (const float*)&shB[qq][loc];
                    float k = fB[2 + l];
                    k = fmaf(qxs[q], fA[0 + l], k);
                    k = fmaf(qys[q], fA[2 + l], k);
                    k = fmaf(qzs[q], fB[0 + l], k);
                    if (k < best) { best = k; bj = j; }
                }
                int jp = bj >> 1, l = bj & 1;
                int qq = jp >> 8, loc = jp & (QJP - 1);
                const float* fA = (const float*)&shA[qq][loc];
                const float* fB = (const float*)&shB[qq][loc];
                sl += smooth_l1(qxs[q], -0.5f * fA[0 + l]);
                sl += smooth_l1(qys[q], -0.5f * fA[2 + l]);
                sl += smooth_l1(qzs[q], -0.5f * fB[0 + l]);
            }
        }
        cx = qx0 + qx1; cy = qy0 + qy1; cz = qz0 + qz1;
    }

    // Deterministic block reduction (fixed tree order).
    red4[tid] = make_float4(sl, cx, cy, cz);
    __syncthreads();
    for (int s = TPB / 2; s > 0; s >>= 1) {
        if (tid < s) {
            float4 a = red4[tid];
            float4 b = red4[tid + s];
            red4[tid] = make_float4(a.x + b.x, a.y + b.y, a.z + b.z, a.w + b.w);
        }
        __syncthreads();
    }
    if (tid == 0) {
        float4 r = red4[0];
        g_loss_part[blk]    = r.x;
        g_cent_part[blk][0] = r.y;
        g_cent_part[blk][1] = r.z;
        g_cent_part[blk][2] = r.w;
        __threadfence();
        unsigned int v = atomicAdd(&g_ctr, 1u);
        is_last = (v == NBLK - 1) ? 1u : 0u;
    }
    __syncthreads();

    // Last block finalizes (deterministic; counter self-resets for graph replay).
    if (is_last && tid < 32) {
        __threadfence();
        const int t = tid;
        float lp = 0.0f, lc = 0.0f;
        if (t < NSETS) {
            float s = 0.0f;
            for (int d = 0; d < 2; d++)
                for (int c = 0; c < CHUNKS; c++)
                    s += g_loss_part[(t * 2 + d) * CHUNKS + c];
            lp = s * (1.0f / (float)(NPTS * 3)) * w[t];

            float pc0 = 0, pc1 = 0, pc2 = 0, tc0 = 0, tc1 = 0, tc2 = 0;
            for (int c = 0; c < CHUNKS; c++) {
                int b0 = (t * 2 + 0) * CHUNKS + c;   // dir 0 queries = X_v
                int b1 = (t * 2 + 1) * CHUNKS + c;   // dir 1 queries = target
                pc0 += g_cent_part[b0][0]; pc1 += g_cent_part[b0][1]; pc2 += g_cent_part[b0][2];
                tc0 += g_cent_part[b1][0]; tc1 += g_cent_part[b1][1]; tc2 += g_cent_part[b1][2];
            }
            const float inv_n = 1.0f / (float)NPTS;
            lc += smooth_l1(pc0 * inv_n, tc0 * inv_n);
            lc += smooth_l1(pc1 * inv_n, tc1 * inv_n);
            lc += smooth_l1(pc2 * inv_n, tc2 * inv_n);
        }
#pragma unroll
        for (int o = 16; o > 0; o >>= 1) {
            lp += __shfl_down_sync(0xffffffff, lp, o);
            lc += __shfl_down_sync(0xffffffff, lc, o);
        }
        if (t == 0) {
            out[0] = lp * 0.5f;          // / B
            out[1] = lc * (1.0f / 6.0f); // / (B*3)
            g_ctr = 0;                   // reset for next graph replay
        }
    }
}

extern "C" void kernel_launch(void* const* d_in, const int* in_sizes, int n_in,
                              void* d_out, int out_size) {
    const float* Xv = (const float*)d_in[0];
    const float* Tv = (const float*)d_in[1];
    const float* w  = (const float*)d_in[2];
    float* out = (float*)d_out;

    chamfer_kernel<<<NBLK, TPB>>>(Xv, Tv, w, out);
}